// round 4
// baseline (speedup 1.0000x reference)
#include <cuda_runtime.h>
#include <cstdint>
#include <math.h>

typedef unsigned long long ull;

static constexpr int B_ROWS = 262144;
static constexpr int L_STEPS = 20;
static constexpr int TPB = 128;
static constexpr int GRID = B_ROWS / TPB;   // 2048

// ---- shared memory layout (floats) ----
// sWd    [50*90]   @ 0        (4500)
// sW1    [100*52]  @ 4500     (5200)  padded stride 52 -> rows 16B aligned
// sWdr   [50*52]   @ 9700     (2600)  padded stride 52
// sW2    [100]     @ 12300
// sbd    [50]      @ 12400
// sbdr   [50]      @ 12450
// sb1    [100]     @ 12500
// sWfc   [100]     @ 12600
// smisc  [4]       @ 12700    (b2, bfc0, bfc1)
// sNoise [2*6400]  @ 12704    (double-buffered 128x50 noise tile)
static constexpr int OFF_WD    = 0;
static constexpr int OFF_W1    = 4500;
static constexpr int OFF_WDR   = 9700;
static constexpr int OFF_W2    = 12300;
static constexpr int OFF_BD    = 12400;
static constexpr int OFF_BDR   = 12450;
static constexpr int OFF_B1    = 12500;
static constexpr int OFF_WFC   = 12600;
static constexpr int OFF_MISC  = 12700;
static constexpr int OFF_NOISE = 12704;
static constexpr int SMEM_FLOATS = OFF_NOISE + 2 * 6400;     // 25504
static constexpr int SMEM_BYTES  = SMEM_FLOATS * 4;          // 102016

// ---- packed f32x2 helpers (Blackwell 2x-fp32 path; PTX-only per SASS_QUICKREF) ----
static __device__ __forceinline__ ull ffma2(ull a, ull b, ull c) {
    ull d;
    asm("fma.rn.f32x2 %0, %1, %2, %3;" : "=l"(d) : "l"(a), "l"(b), "l"(c));
    return d;
}
static __device__ __forceinline__ ull pack2(float lo, float hi) {
    ull r;
    asm("mov.b64 %0, {%1, %2};" : "=l"(r) : "f"(lo), "f"(hi));
    return r;
}
static __device__ __forceinline__ void unpack2(ull v, float& lo, float& hi) {
    asm("mov.b64 {%0, %1}, %2;" : "=f"(lo), "=f"(hi) : "l"(v));
}

static __device__ __forceinline__ unsigned smem_u32(const void* p) {
    return (unsigned)__cvta_generic_to_shared(p);
}
static __device__ __forceinline__ void cp16(void* sdst, const void* gsrc) {
    asm volatile("cp.async.cg.shared.global [%0], [%1], 16;"
                 :: "r"(smem_u32(sdst)), "l"(gsrc) : "memory");
}

// Packed dot over a 50-float row (16B-aligned, stride-52 padded) with packed state v[25].
// 12 x LDS.128 (two f32x2 each) + 1 x LDS.64, 25 fma2. Weight loads broadcast (all lanes same addr).
static __device__ __forceinline__ ull dot25_v(const float* __restrict__ wrow,
                                              const ull* __restrict__ v) {
    const ulonglong2* w2 = (const ulonglong2*)wrow;
    ull a = 0ull;   // (0.0f, 0.0f)
#pragma unroll
    for (int q = 0; q < 12; ++q) {
        ulonglong2 w = w2[q];
        a = ffma2(w.x, v[2 * q],     a);
        a = ffma2(w.y, v[2 * q + 1], a);
    }
    a = ffma2(*(const ull*)(wrow + 48), v[24], a);
    return a;
}

__global__ void __launch_bounds__(TPB, 2)
sdenet_kernel(const float* __restrict__ x,      // [B,90]
              const float* __restrict__ Wd,     // [50,90]
              const float* __restrict__ bd,     // [50]
              const float* __restrict__ Wdrift, // [50,50]
              const float* __restrict__ bdrift, // [50]
              const float* __restrict__ W1,     // [100,50]
              const float* __restrict__ b1,     // [100]
              const float* __restrict__ W2,     // [1,100]
              const float* __restrict__ b2,     // [1]
              const float* __restrict__ Wfc,    // [2,50]
              const float* __restrict__ bfc,    // [2]
              const float* __restrict__ noise,  // [L,B,50]
              float* __restrict__ out)          // [2*B] = mean(B) ++ sigma(B)
{
    extern __shared__ float smem[];
    float* sWd   = smem + OFF_WD;
    float* sW1   = smem + OFF_W1;
    float* sWdr  = smem + OFF_WDR;
    float* sW2   = smem + OFF_W2;
    float* sbd   = smem + OFF_BD;
    float* sbdr  = smem + OFF_BDR;
    float* sb1   = smem + OFF_B1;
    float* sWfc  = smem + OFF_WFC;
    float* smisc = smem + OFF_MISC;
    float* sNoise = smem + OFF_NOISE;

    const int tid = threadIdx.x;
    const int row = blockIdx.x * TPB + tid;
    const size_t rowBase = (size_t)blockIdx.x * TPB;

    // ---- stage weights to SMEM (cooperative, one-time) ----
    for (int i = tid; i < 4500; i += TPB) sWd[i] = Wd[i];
    for (int i = tid; i < 5000; i += TPB) {
        int m = i / 50, k = i - m * 50;
        sW1[m * 52 + k] = W1[i];
    }
    for (int i = tid; i < 2500; i += TPB) {
        int j = i / 50, k = i - j * 50;
        sWdr[j * 52 + k] = Wdrift[i];
    }
    if (tid < 100) sW2[tid]  = W2[tid];
    if (tid < 100) sb1[tid]  = b1[tid];
    if (tid < 100) sWfc[tid] = Wfc[tid];
    if (tid < 50)  sbd[tid]  = bd[tid];
    if (tid < 50)  sbdr[tid] = bdrift[tid];
    if (tid == 0) { smisc[0] = b2[0]; smisc[1] = bfc[0]; smisc[2] = bfc[1]; }

    // ---- prefetch noise tile for step 0 into buffer 0 (25.6 KB, contiguous, coalesced) ----
    {
        const float* nsrc = noise + rowBase * 50;   // l=0
        for (int i = tid; i < 1600; i += TPB)
            cp16(sNoise + i * 4, nsrc + i * 4);
        asm volatile("cp.async.commit_group;" ::: "memory");
    }
    __syncthreads();

    // ================= prologue: out0 = x @ Wd^T + bd (packed over k) =================
    // x row in 3 chunks of 15 f32x2-pairs; two packed accumulator chains per output pair.
    const ull* xr = (const ull*)(x + (size_t)row * 90);  // 360*row bytes, 8B aligned
    ull acc0[25], acc1[25];
#pragma unroll
    for (int p = 0; p < 25; ++p) { acc0[p] = 0ull; acc1[p] = 0ull; }

    for (int c = 0; c < 3; ++c) {
        ull xv[15];
#pragma unroll
        for (int t = 0; t < 15; ++t) xv[t] = xr[c * 15 + t];
#pragma unroll
        for (int p = 0; p < 25; ++p) {
            const ull* w0 = (const ull*)(sWd + (2 * p) * 90) + c * 15;
            const ull* w1 = (const ull*)(sWd + (2 * p + 1) * 90) + c * 15;
            ull a0 = acc0[p], a1 = acc1[p];
#pragma unroll
            for (int t = 0; t < 15; ++t) {
                a0 = ffma2(w0[t], xv[t], a0);
                a1 = ffma2(w1[t], xv[t], a1);
            }
            acc0[p] = a0; acc1[p] = a1;
        }
    }

    ull out2[25];   // state: out[2p], out[2p+1] packed
#pragma unroll
    for (int p = 0; p < 25; ++p) {
        float l0, h0, l1, h1;
        unpack2(acc0[p], l0, h0);
        unpack2(acc1[p], l1, h1);
        out2[p] = pack2(l0 + h0 + sbd[2 * p], l1 + h1 + sbd[2 * p + 1]);
    }

    // ============ diffusion = 0.5*sigmoid(relu(out@W1^T+b1) @ W2^T + b2) ============
    // h never materialized: fold each h[m] straight into the W2 dot (rolled m-loop).
    float dacc = smisc[0];
#pragma unroll 2
    for (int m = 0; m < 100; ++m) {
        ull a = dot25_v(sW1 + m * 52, out2);
        float lo, hi; unpack2(a, lo, hi);
        float hm = fmaxf(lo + hi + sb1[m], 0.0f);
        dacc = fmaf(sW2[m], hm, dacc);
    }
    const float dt   = 4.0f / 20.0f;
    const float sqdt = sqrtf(dt);
    const float diff = 0.5f / (1.0f + expf(-dacc));
    const ull ds2 = pack2(diff * sqdt, diff * sqdt);
    const ull dt2 = pack2(dt, dt);

    // ================= main SDE loop: 20 steps, double-buffered noise =================
    for (int l = 0; l < L_STEPS; ++l) {
        const int cur = l & 1;
        if (l + 1 < L_STEPS) {
            const float* nsrc = noise + ((size_t)(l + 1) * B_ROWS + rowBase) * 50;
            float* dst = sNoise + ((l + 1) & 1) * 6400;
            for (int i = tid; i < 1600; i += TPB)
                cp16(dst + i * 4, nsrc + i * 4);
            asm volatile("cp.async.commit_group;" ::: "memory");
            asm volatile("cp.async.wait_group 1;" ::: "memory");
        } else {
            asm volatile("cp.async.wait_group 0;" ::: "memory");
        }
        __syncthreads();

        const ull* nrow = (const ull*)(sNoise + cur * 6400 + tid * 50);
        ull dnew[25];
#pragma unroll
        for (int p = 0; p < 25; ++p) {
            ull a0 = dot25_v(sWdr + (2 * p) * 52, out2);
            ull a1 = dot25_v(sWdr + (2 * p + 1) * 52, out2);
            float l0, h0, l1, h1;
            unpack2(a0, l0, h0);
            unpack2(a1, l1, h1);
            float s0 = fmaxf(l0 + h0 + sbdr[2 * p], 0.0f);
            float s1 = fmaxf(l1 + h1 + sbdr[2 * p + 1], 0.0f);
            ull nv = ffma2(dt2, pack2(s0, s1), out2[p]);   // out + dt*relu(drift)
            dnew[p] = ffma2(ds2, nrow[p], nv);             // + diff*sqdt*noise
        }
#pragma unroll
        for (int p = 0; p < 25; ++p) out2[p] = dnew[p];
        __syncthreads();   // buffer 'cur' may be overwritten next iteration
    }

    // ================= epilogue: relu(out) @ Wfc^T + bfc -> (mean, sigma) =================
    ull rr[25];
#pragma unroll
    for (int p = 0; p < 25; ++p) {
        float lo, hi; unpack2(out2[p], lo, hi);
        rr[p] = pack2(fmaxf(lo, 0.0f), fmaxf(hi, 0.0f));
    }
    const ull* w0 = (const ull*)(sWfc);        // Wfc row 0
    const ull* w1 = (const ull*)(sWfc + 50);   // Wfc row 1 (200B offset, 8B aligned)
    ull a0 = 0ull, a1 = 0ull;
#pragma unroll
    for (int p = 0; p < 25; ++p) {
        a0 = ffma2(w0[p], rr[p], a0);
        a1 = ffma2(w1[p], rr[p], a1);
    }
    float m0, m1, z0, z1;
    unpack2(a0, m0, m1);
    unpack2(a1, z0, z1);
    const float mean = m0 + m1 + smisc[1];
    const float z    = z0 + z1 + smisc[2];
    const float sp   = log1pf(expf(-fabsf(z))) + fmaxf(z, 0.0f);  // stable softplus

    out[row] = mean;
    out[B_ROWS + row] = sp + 0.001f;
}

extern "C" void kernel_launch(void* const* d_in, const int* in_sizes, int n_in,
                              void* d_out, int out_size) {
    (void)in_sizes; (void)n_in; (void)out_size;
    const float* x      = (const float*)d_in[0];
    const float* Wd     = (const float*)d_in[1];
    const float* bd     = (const float*)d_in[2];
    const float* Wdrift = (const float*)d_in[3];
    const float* bdrift = (const float*)d_in[4];
    const float* W1     = (const float*)d_in[5];
    const float* b1     = (const float*)d_in[6];
    const float* W2     = (const float*)d_in[7];
    const float* b2     = (const float*)d_in[8];
    const float* Wfc    = (const float*)d_in[9];
    const float* bfc    = (const float*)d_in[10];
    const float* noise  = (const float*)d_in[11];
    float* out = (float*)d_out;

    cudaFuncSetAttribute(sdenet_kernel,
                         cudaFuncAttributeMaxDynamicSharedMemorySize, SMEM_BYTES);
    sdenet_kernel<<<GRID, TPB, SMEM_BYTES>>>(x, Wd, bd, Wdrift, bdrift,
                                             W1, b1, W2, b2, Wfc, bfc, noise, out);
}